// round 17
// baseline (speedup 1.0000x reference)
#include <cuda_runtime.h>
#include <cuda_fp16.h>

#define NMAX   100000
#define EMAX   1600000
#define DIN    64
#define NHEAD  4
#define HDIM   16
#define FEAT   64   // NHEAD*HDIM
#define ROW    80   // augmented width: 64 h | u | v+off | as0..3 | ad0..3(+ba) | 6 pad
#define SCAN_B 1024
#define NBINS  64
#define FLAGOFF  NMAX          // scan publish flags at g_degfv[NMAX + b]
#define BINOFF  (NMAX + 128)   // degree-bin counters at g_degfv[NMAX+128 + bin]

// -------- scratch (static device globals; no allocations allowed) ----------
__device__ __align__(16) static __half g_h[(size_t)NMAX * FEAT];
__device__ __align__(16) static float2 g_uas[NMAX * NHEAD];  // (u, as_head)
__device__ __align__(16) static float2 g_vad[NMAX * NHEAD];  // (v+off, ad_head+ba)

__device__ __align__(16) static float g_Wp[DIN * ROW];  // augmented weights
__device__ __align__(16) static float g_bp[ROW];        // augmented bias

__device__ static int g_degfv[NMAX + 256];   // deg | scan flags | degree bins
__device__ static int g_cursor[NMAX];
__device__ static int g_offs[NMAX + 1];
__device__ static int g_srcs[EMAX];
__device__ static int g_nodeorder[NMAX];     // nodes sorted by degree

// ---------------------------------------------------------------------------
// 1) Build W' (64x80) + b'(80): grid=8 x 640 (8 rows/block, 1 thread/col).
//    Cols: c<64: Wl[j][c]; 64: cu; 65: cv; 66+h: Wl_h@Wa_s; 70+h: Wl_h@Wa_d.
//    Bias: c<64: bl; 65: off; 66+h: bl.Wa_s; 70+h: bl.Wa_d + ba; else 0.
// ---------------------------------------------------------------------------
__global__ void __launch_bounds__(640)
precompute_kernel(const float* __restrict__ Wl, const float* __restrict__ bl,
                  const float* __restrict__ Wa, const float* __restrict__ ba,
                  const float* __restrict__ Wd, const float* __restrict__ bd,
                  const float* __restrict__ Wf, const float* __restrict__ bf) {
    __shared__ float wfu[DIN], wfv[DIN], s_wa[2 * HDIM];
    int tid = threadIdx.x;
    if (tid < DIN) {
        float f0 = Wf[tid], f1 = Wf[DIN + tid], f2 = Wf[2 * DIN + tid];
        wfu[tid] = f0 + f2;
        wfv[tid] = f1 - f2;
    }
    if (tid < 2 * HDIM) s_wa[tid] = Wa[tid];
    __syncthreads();

    int j = blockIdx.x * 8 + tid / ROW;   // weight row 0..63
    int c = tid % ROW;                    // output col 0..79

    const float* wlrow = Wl + j * DIN;
    float w = 0.f;
    if (c < 64) {
        w = wlrow[c];
    } else if (c == 64) {
        const float* wd = Wd + j * DIN;
#pragma unroll 8
        for (int k = 0; k < DIN; k++) w += wd[k] * wfu[k];
    } else if (c == 65) {
        const float* wd = Wd + j * DIN;
#pragma unroll 8
        for (int k = 0; k < DIN; k++) w += wd[k] * wfv[k];
    } else if (c < 70) {
        int h = c - 66;
#pragma unroll
        for (int k = 0; k < HDIM; k++) w += wlrow[h * HDIM + k] * s_wa[k];
    } else if (c < 74) {
        int h = c - 70;
#pragma unroll
        for (int k = 0; k < HDIM; k++) w += wlrow[h * HDIM + k] * s_wa[HDIM + k];
    }
    g_Wp[j * ROW + c] = w;

    if (j == 0) {
        float b = 0.f;
        if (c < 64) {
            b = bl[c];
        } else if (c == 65) {
            b = bf[0];
            for (int k = 0; k < DIN; k++) b += bd[k] * (wfu[k] + wfv[k]);
        } else if (c >= 66 && c < 70) {
            int h = c - 66;
#pragma unroll
            for (int k = 0; k < HDIM; k++) b += bl[h * HDIM + k] * s_wa[k];
        } else if (c >= 70 && c < 74) {
            int h = c - 70;
#pragma unroll
            for (int k = 0; k < HDIM; k++) b += bl[h * HDIM + k] * s_wa[HDIM + k];
            b += ba[0];
        }
        g_bp[c] = b;
    }
}

// ---------------------------------------------------------------------------
// 2) Degree histogram over dst, 4 edges/thread (deg zeroed by memsetAsync).
// ---------------------------------------------------------------------------
__global__ void hist_kernel(const int* __restrict__ dst, int E) {
    int q = blockIdx.x * blockDim.x + threadIdx.x;
    int e = q * 4;
    if (e + 3 < E) {
        int4 d4 = *reinterpret_cast<const int4*>(dst + e);
        atomicAdd(&g_degfv[d4.x], 1);
        atomicAdd(&g_degfv[d4.y], 1);
        atomicAdd(&g_degfv[d4.z], 1);
        atomicAdd(&g_degfv[d4.w], 1);
    } else {
        for (int k = e; k < E; k++) atomicAdd(&g_degfv[dst[k]], 1);
    }
}

// ---------------------------------------------------------------------------
// 3) Single-pass exclusive scan + degree-bin counting.
// ---------------------------------------------------------------------------
__global__ void scan_onepass_kernel(int N, int NB) {
    __shared__ int sm[SCAN_B];
    __shared__ int s_base;
    int b = blockIdx.x;
    int tid = threadIdx.x;
    int idx = b * SCAN_B + tid;

    int v = (idx < N) ? g_degfv[idx] : 0;
    if (idx < N) atomicAdd(&g_degfv[BINOFF + min(v, NBINS - 1)], 1);
    sm[tid] = v;
    __syncthreads();
#pragma unroll
    for (int o = 1; o < SCAN_B; o <<= 1) {
        int tmp = (tid >= o) ? sm[tid - o] : 0;
        __syncthreads();
        sm[tid] += tmp;
        __syncthreads();
    }
    int incl = sm[tid];
    int agg = sm[SCAN_B - 1];

    if (tid == 0) {
        __threadfence();
        atomicExch(&g_degfv[FLAGOFF + b], agg + 1);
    }
    if (tid < 32) {
        int contrib = 0;
        for (int t = tid; t < b; t += 32) {
            int fv;
            do { fv = atomicAdd(&g_degfv[FLAGOFF + t], 0); } while (fv == 0);
            contrib += fv - 1;
        }
#pragma unroll
        for (int o = 16; o > 0; o >>= 1)
            contrib += __shfl_down_sync(0xffffffffu, contrib, o);
        if (tid == 0) s_base = contrib;
    }
    __syncthreads();
    int base = s_base;

    if (idx < N) {
        int off = base + incl - v;
        g_offs[idx] = off;
        g_cursor[idx] = off;
    }
    if (b == NB - 1 && tid == 0) g_offs[N] = base + agg;
}

// ---------------------------------------------------------------------------
// 3b) Exclusive scan of the 64 degree bins (1 block, in-place -> cursors).
// ---------------------------------------------------------------------------
__global__ void binscan_kernel() {
    __shared__ int sm[NBINS];
    int t = threadIdx.x;   // 64
    int v = g_degfv[BINOFF + t];
    sm[t] = v;
    __syncthreads();
#pragma unroll
    for (int o = 1; o < NBINS; o <<= 1) {
        int tmp = (t >= o) ? sm[t - o] : 0;
        __syncthreads();
        sm[t] += tmp;
        __syncthreads();
    }
    g_degfv[BINOFF + t] = sm[t] - v;   // exclusive base -> cursor
}

// ---------------------------------------------------------------------------
// 3c) Scatter node ids into degree-sorted order.
// ---------------------------------------------------------------------------
__global__ void order_kernel(int N) {
    int n = blockIdx.x * blockDim.x + threadIdx.x;
    if (n >= N) return;
    int bin = min(g_degfv[n], NBINS - 1);
    int pos = atomicAdd(&g_degfv[BINOFF + bin], 1);
    g_nodeorder[pos] = n;
}

// ---------------------------------------------------------------------------
// 4) Scatter src ids into dst-sorted order, 4 edges/thread.
// ---------------------------------------------------------------------------
__global__ void scatter_kernel(const int* __restrict__ src,
                               const int* __restrict__ dst, int E) {
    int q = blockIdx.x * blockDim.x + threadIdx.x;
    int e = q * 4;
    if (e + 3 < E) {
        int4 s4 = *reinterpret_cast<const int4*>(src + e);
        int4 d4 = *reinterpret_cast<const int4*>(dst + e);
        g_srcs[atomicAdd(&g_cursor[d4.x], 1)] = s4.x;
        g_srcs[atomicAdd(&g_cursor[d4.y], 1)] = s4.y;
        g_srcs[atomicAdd(&g_cursor[d4.z], 1)] = s4.z;
        g_srcs[atomicAdd(&g_cursor[d4.w], 1)] = s4.w;
    } else {
        for (int k = e; k < E; k++)
            g_srcs[atomicAdd(&g_cursor[dst[k]], 1)] = src[k];
    }
}

// ---------------------------------------------------------------------------
// 5) Node GEMM: x[N,64] @ W'[64,80]. 8-thread groups own 8 nodes; thread c
//    computes 10 columns for all 8 nodes.
// ---------------------------------------------------------------------------
__global__ void __launch_bounds__(128)
node_kernel(const float* __restrict__ x, int N) {
    __shared__ __align__(16) float s_wp[DIN * ROW];
    __shared__ __align__(16) float s_bp[ROW];

    int tid = threadIdx.x;
    {
        const float4* src4 = reinterpret_cast<const float4*>(g_Wp);
        float4* dst4 = reinterpret_cast<float4*>(s_wp);
        for (int i = tid; i < DIN * ROW / 4; i += 128) dst4[i] = src4[i];
        if (tid < ROW) s_bp[tid] = g_bp[tid];
    }
    __syncthreads();

    int grp = tid >> 3;
    int c = tid & 7;
    int nbase = blockIdx.x * 128 + grp * 8;
    if (nbase >= N) return;

    unsigned long long acc[8][5];
    {
        const unsigned long long* bp =
            reinterpret_cast<const unsigned long long*>(&s_bp[c * 10]);
#pragma unroll
        for (int q = 0; q < 5; q++) {
            unsigned long long b = bp[q];
#pragma unroll
            for (int m = 0; m < 8; m++) acc[m][q] = b;
        }
    }

    const float4* xr[8];
#pragma unroll
    for (int m = 0; m < 8; m++) {
        int nm = min(nbase + m, N - 1);
        xr[m] = reinterpret_cast<const float4*>(x + (size_t)nm * DIN);
    }

#pragma unroll 1
    for (int i4 = 0; i4 < DIN / 4; i4++) {
        float4 xv[8];
#pragma unroll
        for (int m = 0; m < 8; m++) xv[m] = xr[m][i4];
#pragma unroll
        for (int j = 0; j < 4; j++) {
            int i = i4 * 4 + j;
            unsigned long long xs[8];
#pragma unroll
            for (int m = 0; m < 8; m++) {
                float xi = (j == 0) ? xv[m].x : (j == 1) ? xv[m].y
                         : (j == 2) ? xv[m].z : xv[m].w;
                asm("mov.b64 %0, {%1, %1};" : "=l"(xs[m]) : "f"(xi));
            }
            const unsigned long long* wrow =
                reinterpret_cast<const unsigned long long*>(&s_wp[i * ROW + c * 10]);
#pragma unroll
            for (int q = 0; q < 5; q++) {
                unsigned long long wv = wrow[q];
#pragma unroll
                for (int m = 0; m < 8; m++)
                    asm("fma.rn.f32x2 %0, %1, %2, %0;"
                        : "+l"(acc[m][q]) : "l"(wv), "l"(xs[m]));
            }
        }
    }

    int lane6 = (tid & ~7) | 6;
#pragma unroll
    for (int m = 0; m < 8; m++) {
        int n = nbase + m;
        float val[10];
#pragma unroll
        for (int q = 0; q < 5; q++)
            asm("mov.b64 {%0, %1}, %2;"
                : "=f"(val[2 * q]), "=f"(val[2 * q + 1]) : "l"(acc[m][q]));

        float vbrd = __shfl_sync(0xffffffffu, val[5], lane6);

        if (n < N) {
            if (c < 6) {
                __half2* hp = reinterpret_cast<__half2*>(&g_h[(size_t)n * FEAT + c * 10]);
#pragma unroll
                for (int q = 0; q < 5; q++)
                    hp[q] = __floats2half2_rn(val[2 * q], val[2 * q + 1]);
            } else if (c == 6) {
                __half2* hp = reinterpret_cast<__half2*>(&g_h[(size_t)n * FEAT + 60]);
                hp[0] = __floats2half2_rn(val[0], val[1]);
                hp[1] = __floats2half2_rn(val[2], val[3]);
                float u = val[4];
#pragma unroll
                for (int h = 0; h < NHEAD; h++)
                    g_uas[n * NHEAD + h] = make_float2(u, val[6 + h]);
            } else if (c == 7) {
#pragma unroll
                for (int h = 0; h < NHEAD; h++)
                    g_vad[n * NHEAD + h] = make_float2(vbrd, val[h]);
            }
        }
    }
}

// ---------------------------------------------------------------------------
// 6) CSR reduce over degree-sorted nodes: 4 threads per node (lane == head).
//    All 8 nodes in a warp have (near-)equal degree -> no wasted iterations.
// ---------------------------------------------------------------------------
__global__ void __launch_bounds__(256)
reduce_kernel(float* __restrict__ out, int N) {
    int gid = blockIdx.x * blockDim.x + threadIdx.x;
    int i = gid >> 2;
    if (i >= N) return;
    int head = gid & 3;
    int n = __ldg(&g_nodeorder[i]);

    int beg = __ldg(&g_offs[n]);
    int end = __ldg(&g_offs[n + 1]);

    float2 vad = __ldg(&g_vad[n * NHEAD + head]);
    float vofs = vad.x;
    float adb  = vad.y;

    float acc[16];
#pragma unroll
    for (int k = 0; k < 16; k++) acc[k] = 0.f;
    float dsum = 0.f;

    if (beg < end) {
        int s = __ldg(&g_srcs[beg]);
        for (int p = beg; p < end; p++) {
            int s_next = (p + 1 < end) ? __ldg(&g_srcs[p + 1]) : 0;
            float2 ua = __ldg(&g_uas[s * NHEAD + head]);
            const uint4* hp = reinterpret_cast<const uint4*>(
                &g_h[(size_t)s * FEAT + head * HDIM]);
            uint4 raw0 = hp[0];
            uint4 raw1 = hp[1];

            float arg = ua.x + vofs;
            float sg = (arg > 0.f) ? 1.f : ((arg < 0.f) ? -1.f : 0.f);
            float al = sg * ua.y + adb;
            al = (al > 0.f) ? al : 0.01f * al;          // leaky_relu
            float w = __expf(al);
            float ws = w * sg;

            const __half2* c0 = reinterpret_cast<const __half2*>(&raw0);
            const __half2* c1 = reinterpret_cast<const __half2*>(&raw1);
#pragma unroll
            for (int q = 0; q < 4; q++) {
                float2 f0 = __half22float2(c0[q]);
                float2 f1 = __half22float2(c1[q]);
                acc[q * 2 + 0] += ws * f0.x;
                acc[q * 2 + 1] += ws * f0.y;
                acc[8 + q * 2 + 0] += ws * f1.x;
                acc[8 + q * 2 + 1] += ws * f1.y;
            }
            dsum += w;
            s = s_next;
        }
    }

    float inv = 1.f / fmaxf(dsum, 1e-16f);
    float* op = &out[(size_t)n * FEAT + head * HDIM];
#pragma unroll
    for (int q = 0; q < 4; q++)
        reinterpret_cast<float4*>(op)[q] =
            make_float4(acc[q * 4 + 0] * inv, acc[q * 4 + 1] * inv,
                        acc[q * 4 + 2] * inv, acc[q * 4 + 3] * inv);
}

// ---------------------------------------------------------------------------
extern "C" void kernel_launch(void* const* d_in, const int* in_sizes, int n_in,
                              void* d_out, int out_size) {
    const float* x   = (const float*)d_in[0];
    const int*   src = (const int*)  d_in[1];
    const int*   dst = (const int*)  d_in[2];
    const float* Wl  = (const float*)d_in[3];
    const float* bl  = (const float*)d_in[4];
    const float* Wa  = (const float*)d_in[5];
    const float* ba  = (const float*)d_in[6];
    const float* Wd  = (const float*)d_in[7];
    const float* bd  = (const float*)d_in[8];
    const float* Wf  = (const float*)d_in[9];
    const float* bf  = (const float*)d_in[10];
    float* out = (float*)d_out;

    int N = in_sizes[0] / DIN;
    int E = in_sizes[1];
    int NB = (N + SCAN_B - 1) / SCAN_B;

    static cudaStream_t s_side = nullptr;
    static cudaEvent_t  ev_fork = nullptr, ev_join = nullptr;
    static int* p_degfv = nullptr;
    if (s_side == nullptr) {
        cudaStreamCreateWithFlags(&s_side, cudaStreamNonBlocking);
        cudaEventCreateWithFlags(&ev_fork, cudaEventDisableTiming);
        cudaEventCreateWithFlags(&ev_join, cudaEventDisableTiming);
        cudaGetSymbolAddress((void**)&p_degfv, g_degfv);
    }

    cudaEventRecord(ev_fork, 0);
    cudaStreamWaitEvent(s_side, ev_fork, 0);

    // zero deg + flags + bins in one memset
    cudaMemsetAsync(p_degfv, 0, (size_t)(NMAX + 256) * sizeof(int), s_side);
    {
        int qthreads = (E + 3) / 4;
        hist_kernel<<<(qthreads + 255) / 256, 256, 0, s_side>>>(dst, E);
    }
    scan_onepass_kernel<<<NB, SCAN_B, 0, s_side>>>(N, NB);
    binscan_kernel<<<1, NBINS, 0, s_side>>>();
    order_kernel<<<(N + 255) / 256, 256, 0, s_side>>>(N);
    {
        int qthreads = (E + 3) / 4;
        scatter_kernel<<<(qthreads + 255) / 256, 256, 0, s_side>>>(src, dst, E);
    }
    cudaEventRecord(ev_join, s_side);

    precompute_kernel<<<8, 640>>>(Wl, bl, Wa, ba, Wd, bd, Wf, bf);
    node_kernel<<<(N + 127) / 128, 128>>>(x, N);

    cudaStreamWaitEvent(0, ev_join, 0);
    long long threads = (long long)N * 4;
    int blocks = (int)((threads + 255) / 256);
    reduce_kernel<<<blocks, 256>>>(out, N);
}